// round 1
// baseline (speedup 1.0000x reference)
#include <cuda_runtime.h>
#include <math.h>

// AnomalyAttention: B=2, L=2048, H=8, E=64, band |i-j| < 64.
// Inputs (metadata order): queries [B,L,H,E] f32, keys [B,L,H,E] f32,
// values [B,L,H,E] f32, sigma [B,L,H] f32 (UNUSED), attn_mask bool (UNUSED).
// Output: concat( V [B,L,H,E] f32 , series [B,H,L,L] f32 ).

#define BN 2
#define HN 8
#define LN 2048
#define EN 64
#define RT 64          // rows per block
#define SPAD 192       // Ss row stride (>= max band span 190)
#define KSTR 65        // K/V/Q smem row stride (65 % 32 == 1 -> conflict-free)

__global__ __launch_bounds__(512, 1)
void anomaly_attn_kernel(const float* __restrict__ Q,
                         const float* __restrict__ K,
                         const float* __restrict__ V,
                         float* __restrict__ out)
{
    extern __shared__ float sm[];
    float* Qs = sm;                          // RT   * KSTR
    float* Ks = Qs + RT * KSTR;              // SPAD * KSTR
    float* Vs = Ks + SPAD * KSTR;            // SPAD * KSTR
    float* Ss = Vs + SPAD * KSTR;            // RT   * SPAD (unnormalized softmax)

    const int bid = blockIdx.x;
    const int t   = bid & 31;          // row tile
    const int h   = (bid >> 5) & 7;
    const int b   = bid >> 8;
    const int i0  = t * RT;
    const int jlo = max(0, i0 - 63);
    const int jhi = min(LN - 1, i0 + RT + 62);   // i0 + 126
    const int span = jhi - jlo + 1;              // <= 190

    const int tid  = threadIdx.x;
    const int lane = tid & 31;
    const int w    = tid >> 5;          // 16 warps, 4 rows each

    // ---- zero the score buffer (out-of-band entries must be 0) ----
    for (int i = tid; i < RT * SPAD; i += 512) Ss[i] = 0.0f;

    // ---- cooperative loads: Q rows [i0, i0+64), K/V rows [jlo, jhi] ----
    {
        const int e  = tid & 63;
        const int r0 = tid >> 6;    // 0..7
        for (int r = r0; r < RT; r += 8) {
            const int gi = i0 + r;
            Qs[r * KSTR + e] = Q[(((size_t)b * LN + gi) * HN + h) * EN + e];
        }
        for (int r = r0; r < span; r += 8) {
            const size_t g = (((size_t)b * LN + (jlo + r)) * HN + h) * EN + e;
            Ks[r * KSTR + e] = K[g];
            Vs[r * KSTR + e] = V[g];
        }
    }
    __syncthreads();

    // ---- per-warp: 4 rows, band-union j range ----
    const int ga   = 4 * w;             // local row base
    const int gia  = i0 + ga;           // global row base
    const int g_lo = max(0, gia - 63) - jlo;            // rel, >= 0
    const int g_hi = min(LN - 1, gia + 66) - jlo;       // rel, inclusive, <= span-1
    const int jr0  = g_lo + lane;

    const float scale = 0.125f;         // 1/sqrt(64)

    // ---- GEMM1: scores[4 rows][5 slots] ----
    float acc[4][5];
#pragma unroll
    for (int r = 0; r < 4; r++)
#pragma unroll
        for (int s = 0; s < 5; s++) acc[r][s] = 0.0f;

    bool vld[5];
#pragma unroll
    for (int s = 0; s < 5; s++) vld[s] = (jr0 + 32 * s) <= g_hi;

    const float* qp0 = Qs + (ga + 0) * KSTR;
    const float* qp1 = Qs + (ga + 1) * KSTR;
    const float* qp2 = Qs + (ga + 2) * KSTR;
    const float* qp3 = Qs + (ga + 3) * KSTR;

#pragma unroll 8
    for (int e = 0; e < EN; e++) {
        const float q0 = qp0[e];
        const float q1 = qp1[e];
        const float q2 = qp2[e];
        const float q3 = qp3[e];
#pragma unroll
        for (int s = 0; s < 5; s++) {
            const float kv = vld[s] ? Ks[(jr0 + 32 * s) * KSTR + e] : 0.0f;
            acc[0][s] = fmaf(q0, kv, acc[0][s]);
            acc[1][s] = fmaf(q1, kv, acc[1][s]);
            acc[2][s] = fmaf(q2, kv, acc[2][s]);
            acc[3][s] = fmaf(q3, kv, acc[3][s]);
        }
    }

    // ---- row max over band (register sweep + warp reduce) ----
    float mx[4] = { -INFINITY, -INFINITY, -INFINITY, -INFINITY };
#pragma unroll
    for (int s = 0; s < 5; s++) {
        const int j = jlo + jr0 + 32 * s;
#pragma unroll
        for (int r = 0; r < 4; r++) {
            const int gi = gia + r;
            const bool c = ((unsigned)(j - gi + 63) <= 126u) && (j < LN);
            if (c) mx[r] = fmaxf(mx[r], acc[r][s] * scale);
        }
    }
#pragma unroll
    for (int off = 16; off > 0; off >>= 1)
#pragma unroll
        for (int r = 0; r < 4; r++)
            mx[r] = fmaxf(mx[r], __shfl_xor_sync(0xffffffffu, mx[r], off));

    // ---- exp + sum, write unnormalized p to smem ----
    float sum[4] = { 0.f, 0.f, 0.f, 0.f };
#pragma unroll
    for (int s = 0; s < 5; s++) {
        const int jr = jr0 + 32 * s;
        const int j  = jlo + jr;
#pragma unroll
        for (int r = 0; r < 4; r++) {
            const int gi = gia + r;
            const bool c = ((unsigned)(j - gi + 63) <= 126u) && (j < LN);
            if (c) {
                const float p = __expf(acc[r][s] * scale - mx[r]);
                sum[r] += p;
                Ss[(ga + r) * SPAD + jr] = p;
            }
        }
    }
#pragma unroll
    for (int off = 16; off > 0; off >>= 1)
#pragma unroll
        for (int r = 0; r < 4; r++)
            sum[r] += __shfl_xor_sync(0xffffffffu, sum[r], off);

    float rinv[4];
#pragma unroll
    for (int r = 0; r < 4; r++) rinv[r] = 1.0f / sum[r];

    __syncwarp();   // make this warp's Ss writes visible warp-wide

    // ---- series output: full 2048-wide row, zeros outside band ----
    float* series = out + (size_t)BN * LN * HN * EN;   // V block is 2,097,152 floats
#pragma unroll
    for (int r = 0; r < 4; r++) {
        const int gi = gia + r;
        const float rv = rinv[r];
        const float* srow = Ss + (ga + r) * SPAD;
        float4* orow = (float4*)(series + ((size_t)((b * HN + h) * LN) + gi) * (size_t)LN);
        for (int c = lane; c < LN / 4; c += 32) {
            const int j0 = 4 * c;
            float4 vv;
            {
                const int j = j0 + 0;
                const bool cc = (unsigned)(j - gi + 63) <= 126u;
                vv.x = cc ? srow[j - jlo] * rv : 0.0f;
            }
            {
                const int j = j0 + 1;
                const bool cc = (unsigned)(j - gi + 63) <= 126u;
                vv.y = cc ? srow[j - jlo] * rv : 0.0f;
            }
            {
                const int j = j0 + 2;
                const bool cc = (unsigned)(j - gi + 63) <= 126u;
                vv.z = cc ? srow[j - jlo] * rv : 0.0f;
            }
            {
                const int j = j0 + 3;
                const bool cc = (unsigned)(j - gi + 63) <= 126u;
                vv.w = cc ? srow[j - jlo] * rv : 0.0f;
            }
            orow[c] = vv;
        }
    }

    // ---- GEMM2: V_out[4 rows][64] = p @ Vs (p==0 outside each row's band) ----
    float a0[4], a1[4];
#pragma unroll
    for (int r = 0; r < 4; r++) { a0[r] = 0.0f; a1[r] = 0.0f; }

    for (int jr = g_lo; jr <= g_hi; jr++) {
        const float v0 = Vs[jr * KSTR + lane];
        const float v1 = Vs[jr * KSTR + 32 + lane];
#pragma unroll
        for (int r = 0; r < 4; r++) {
            const float p = Ss[(ga + r) * SPAD + jr];
            a0[r] = fmaf(p, v0, a0[r]);
            a1[r] = fmaf(p, v1, a1[r]);
        }
    }
#pragma unroll
    for (int r = 0; r < 4; r++) {
        const int gi = gia + r;
        const size_t o = (((size_t)b * LN + gi) * HN + h) * EN;
        out[o + lane]      = a0[r] * rinv[r];
        out[o + 32 + lane] = a1[r] * rinv[r];
    }
}

extern "C" void kernel_launch(void* const* d_in, const int* in_sizes, int n_in,
                              void* d_out, int out_size) {
    const float* Q = (const float*)d_in[0];
    const float* K = (const float*)d_in[1];
    const float* V = (const float*)d_in[2];
    // d_in[3] = sigma (unused), d_in[4] = attn_mask (unused)
    float* out = (float*)d_out;

    const int smem_bytes = (RT * KSTR + 2 * SPAD * KSTR + RT * SPAD) * (int)sizeof(float);
    cudaFuncSetAttribute(anomaly_attn_kernel,
                         cudaFuncAttributeMaxDynamicSharedMemorySize, smem_bytes);

    dim3 grid(BN * HN * (LN / RT));   // 512 blocks
    dim3 block(512);
    anomaly_attn_kernel<<<grid, block, smem_bytes>>>(Q, K, V, out);
}

// round 2
// speedup vs baseline: 1.4081x; 1.4081x over previous
#include <cuda_runtime.h>
#include <math.h>

// AnomalyAttention: B=2, L=2048, H=8, E=64, band |i-j| <= 63.
// out = concat( V [B,L,H,E] f32 , series [B,H,L,L] f32 ).

#define BN 2
#define HN 8
#define LN 2048
#define EN 64
#define RT 64          // rows per block
#define KROWS 192      // padded K/V rows in smem (max span 190, +pair tail)
#define KSTR 66        // K/V/Q smem row stride (even -> LDS.64 aligned; 66%32=2 conflict-free)
#define SPAD 132       // Ss row stride (max warp span 130, even)

typedef unsigned long long u64;

__device__ __forceinline__ u64 fma2(u64 a, u64 b, u64 c) {
    u64 d;
    asm("fma.rn.f32x2 %0, %1, %2, %3;" : "=l"(d) : "l"(a), "l"(b), "l"(c));
    return d;
}
__device__ __forceinline__ u64 pack2(float lo, float hi) {
    u64 d;
    asm("mov.b64 %0, {%1, %2};" : "=l"(d) : "f"(lo), "f"(hi));
    return d;
}
__device__ __forceinline__ float2 unpack2(u64 v) {
    float2 r;
    asm("mov.b64 {%0, %1}, %2;" : "=f"(r.x), "=f"(r.y) : "l"(v));
    return r;
}

__global__ __launch_bounds__(512, 1)
void anomaly_attn_kernel(const float* __restrict__ Q,
                         const float* __restrict__ K,
                         const float* __restrict__ V,
                         float* __restrict__ out)
{
    extern __shared__ float sm[];
    float* Qs = sm;                          // RT    * KSTR
    float* Ks = Qs + RT * KSTR;              // KROWS * KSTR
    float* Vs = Ks + KROWS * KSTR;           // KROWS * KSTR
    float* Ss = Vs + KROWS * KSTR;           // RT    * SPAD  (unnormalized p, warp-local cols)

    const int bid = blockIdx.x;
    const int t   = bid & 31;
    const int h   = (bid >> 5) & 7;
    const int b   = bid >> 8;
    const int i0  = t * RT;
    const int jlo = max(0, i0 - 63);
    const int jhi = min(LN - 1, i0 + RT + 62);
    const int span = jhi - jlo + 1;              // <= 190

    const int tid  = threadIdx.x;
    const int lane = tid & 31;
    const int w    = tid >> 5;          // 16 warps, 4 rows each

    // ---- zero the score buffer ----
    for (int i = tid; i < RT * SPAD; i += 512) Ss[i] = 0.0f;

    // ---- cooperative loads (float4 global, 2x STS.64), zero-pad K/V to KROWS ----
    {
        const int e4 = (tid & 15) * 4;
        const int r0 = tid >> 4;            // 0..31
#pragma unroll
        for (int r = r0; r < RT; r += 32) {
            const float4 v = *(const float4*)&Q[(((size_t)b * LN + (i0 + r)) * HN + h) * EN + e4];
            float2* d = (float2*)(Qs + r * KSTR + e4);
            d[0] = make_float2(v.x, v.y);
            d[1] = make_float2(v.z, v.w);
        }
#pragma unroll
        for (int r = r0; r < KROWS; r += 32) {
            float4 kv = make_float4(0.f, 0.f, 0.f, 0.f);
            float4 vv = make_float4(0.f, 0.f, 0.f, 0.f);
            if (r < span) {
                const size_t g = (((size_t)b * LN + (jlo + r)) * HN + h) * EN + e4;
                kv = *(const float4*)&K[g];
                vv = *(const float4*)&V[g];
            }
            float2* dk = (float2*)(Ks + r * KSTR + e4);
            dk[0] = make_float2(kv.x, kv.y);
            dk[1] = make_float2(kv.z, kv.w);
            float2* dv = (float2*)(Vs + r * KSTR + e4);
            dv[0] = make_float2(vv.x, vv.y);
            dv[1] = make_float2(vv.z, vv.w);
        }
    }
    __syncthreads();

    // ---- per-warp geometry ----
    const int ga    = 4 * w;
    const int gia   = i0 + ga;
    const int g_lo  = max(0, gia - 63) - jlo;           // first K/V row this warp touches
    const int g_hi  = min(LN - 1, gia + 66) - jlo;      // last valid row
    const int spanw = g_hi - g_lo;                      // <= 129
    const int jbase = jlo + g_lo;                       // global j of warp-local col 0

    const float scale = 0.125f;

    // ---- GEMM1 (f32x2): scores[4][5], warp-local col jj = lane + 32*s ----
    u64 acc[4][5];
#pragma unroll
    for (int r = 0; r < 4; r++)
#pragma unroll
        for (int s = 0; s < 5; s++) acc[r][s] = 0ull;

    const float2* kp[5];
#pragma unroll
    for (int s = 0; s < 5; s++) {
        const int row = min(g_lo + lane + 32 * s, KROWS - 1);  // clamp: garbage lanes masked later
        kp[s] = (const float2*)(Ks + row * KSTR);
    }
    const float2* qp0 = (const float2*)(Qs + (ga + 0) * KSTR);
    const float2* qp1 = (const float2*)(Qs + (ga + 1) * KSTR);
    const float2* qp2 = (const float2*)(Qs + (ga + 2) * KSTR);
    const float2* qp3 = (const float2*)(Qs + (ga + 3) * KSTR);

#pragma unroll 8
    for (int e = 0; e < EN / 2; e++) {
        const float2 q0f = qp0[e], q1f = qp1[e], q2f = qp2[e], q3f = qp3[e];
        const u64 q0 = pack2(q0f.x, q0f.y);
        const u64 q1 = pack2(q1f.x, q1f.y);
        const u64 q2 = pack2(q2f.x, q2f.y);
        const u64 q3 = pack2(q3f.x, q3f.y);
#pragma unroll
        for (int s = 0; s < 5; s++) {
            const float2 kf = kp[s][e];
            const u64 kk = pack2(kf.x, kf.y);
            acc[0][s] = fma2(q0, kk, acc[0][s]);
            acc[1][s] = fma2(q1, kk, acc[1][s]);
            acc[2][s] = fma2(q2, kk, acc[2][s]);
            acc[3][s] = fma2(q3, kk, acc[3][s]);
        }
    }

    // horizontal add -> scaled scores
    float sc[4][5];
#pragma unroll
    for (int r = 0; r < 4; r++)
#pragma unroll
        for (int s = 0; s < 5; s++) {
            const float2 a = unpack2(acc[r][s]);
            sc[r][s] = (a.x + a.y) * scale;
        }

    // ---- row max ----
    float mx[4] = { -INFINITY, -INFINITY, -INFINITY, -INFINITY };
#pragma unroll
    for (int s = 0; s < 5; s++) {
        const int jj = lane + 32 * s;
        const int j  = jbase + jj;
#pragma unroll
        for (int r = 0; r < 4; r++) {
            const int gi = gia + r;
            const bool c = (jj <= spanw) && ((unsigned)(j - gi + 63) <= 126u);
            if (c) mx[r] = fmaxf(mx[r], sc[r][s]);
        }
    }
#pragma unroll
    for (int off = 16; off > 0; off >>= 1)
#pragma unroll
        for (int r = 0; r < 4; r++)
            mx[r] = fmaxf(mx[r], __shfl_xor_sync(0xffffffffu, mx[r], off));

    // ---- exp + sum; unnormalized p -> Ss (warp-local cols) ----
    float sum[4] = { 0.f, 0.f, 0.f, 0.f };
#pragma unroll
    for (int s = 0; s < 5; s++) {
        const int jj = lane + 32 * s;
        const int j  = jbase + jj;
#pragma unroll
        for (int r = 0; r < 4; r++) {
            const int gi = gia + r;
            const bool c = (jj <= spanw) && ((unsigned)(j - gi + 63) <= 126u);
            if (c) {
                const float p = __expf(sc[r][s] - mx[r]);
                sum[r] += p;
                Ss[(ga + r) * SPAD + jj] = p;
            }
        }
    }
#pragma unroll
    for (int off = 16; off > 0; off >>= 1)
#pragma unroll
        for (int r = 0; r < 4; r++)
            sum[r] += __shfl_xor_sync(0xffffffffu, sum[r], off);

    float rinv[4];
#pragma unroll
    for (int r = 0; r < 4; r++) rinv[r] = 1.0f / sum[r];

    __syncwarp();

    // ---- series output: mostly bare zero STG.128, selects only in band chunks ----
    float* series = out + (size_t)BN * LN * HN * EN;
#pragma unroll
    for (int r = 0; r < 4; r++) {
        const int gi  = gia + r;
        const float rv = rinv[r];
        const int blo = max(0, gi - 63);
        const int bhi = min(LN - 1, gi + 63);
        const int c_lo = blo >> 2;
        const int c_hi = bhi >> 2;
        const float* srow = Ss + (ga + r) * SPAD;
        float4* orow = (float4*)(series + ((size_t)((b * HN + h) * LN) + gi) * (size_t)LN);
        for (int c = lane; c < LN / 4; c += 32) {
            float4 vv = make_float4(0.f, 0.f, 0.f, 0.f);
            if (c >= c_lo && c <= c_hi) {
                const int j0 = 4 * c;
#pragma unroll
                for (int u = 0; u < 4; u++) {
                    const int j = j0 + u;
                    const bool cc = (unsigned)(j - gi + 63) <= 126u;
                    const float val = cc ? srow[j - jbase] * rv : 0.0f;
                    if (u == 0) vv.x = val;
                    else if (u == 1) vv.y = val;
                    else if (u == 2) vv.z = val;
                    else vv.w = val;
                }
            }
            __stcs(orow + c, vv);
        }
    }

    // ---- GEMM2 (f32x2 over j-pairs): V_out[4][64] ----
    u64 a0[4], a1[4];
#pragma unroll
    for (int r = 0; r < 4; r++) { a0[r] = 0ull; a1[r] = 0ull; }

    const int niter = (spanw + 2) >> 1;    // jj pairs; tail reads zero-padded Ss/Vs
    for (int it = 0; it < niter; it++) {
        const int jj = 2 * it;
        const int rv0 = g_lo + jj;
        const int rv1 = rv0 + 1;
        const float va0 = Vs[rv0 * KSTR + lane];
        const float vb0 = Vs[rv0 * KSTR + 32 + lane];
        const float va1 = Vs[rv1 * KSTR + lane];
        const float vb1 = Vs[rv1 * KSTR + 32 + lane];
        const u64 vpa = pack2(va0, va1);
        const u64 vpb = pack2(vb0, vb1);
#pragma unroll
        for (int r = 0; r < 4; r++) {
            const float2 pp = *(const float2*)(Ss + (ga + r) * SPAD + jj);
            const u64 pk = pack2(pp.x, pp.y);
            a0[r] = fma2(pk, vpa, a0[r]);
            a1[r] = fma2(pk, vpb, a1[r]);
        }
    }
#pragma unroll
    for (int r = 0; r < 4; r++) {
        const int gi = gia + r;
        const size_t o = (((size_t)b * LN + gi) * HN + h) * EN;
        const float2 x0 = unpack2(a0[r]);
        const float2 x1 = unpack2(a1[r]);
        out[o + lane]      = (x0.x + x0.y) * rinv[r];
        out[o + 32 + lane] = (x1.x + x1.y) * rinv[r];
    }
}

extern "C" void kernel_launch(void* const* d_in, const int* in_sizes, int n_in,
                              void* d_out, int out_size) {
    const float* Q = (const float*)d_in[0];
    const float* K = (const float*)d_in[1];
    const float* V = (const float*)d_in[2];
    float* out = (float*)d_out;

    const int smem_bytes = (RT * KSTR + 2 * KROWS * KSTR + RT * SPAD) * (int)sizeof(float);
    cudaFuncSetAttribute(anomaly_attn_kernel,
                         cudaFuncAttributeMaxDynamicSharedMemorySize, smem_bytes);

    dim3 grid(BN * HN * (LN / RT));   // 512 blocks
    dim3 block(512);
    anomaly_attn_kernel<<<grid, block, smem_bytes>>>(Q, K, V, out);
}